// round 15
// baseline (speedup 1.0000x reference)
#include <cuda_runtime.h>
#include <cuda_bf16.h>
#include <math.h>

// Problem dims (fixed by dataset)
#define BB 64
#define SS 512
#define HH 768
#define LL 9

#define SPLIT 8                 // chunk lanes per token
#define NQ (HH / 32)            // 24 stages (32 features each, 4 rows per chunk-lane)
#define WREG (NQ * LL * 4 + 4)  // 868 floats per chunk region; mod 32 = 4 (bank rotation)

// Chunk c owns global rows { q*32 + c*4 + j }.  x load at stage q: 16B index
// q*8+c -> lanes (t_in*8+c) read 4 x 128B lines per warp LDG (coalesced).
// W staged as per-(stage,col) row-quads: Ws[c*WREG + (q*9+l)*4 + j]
//   = W[(q*32+c*4+j)*9 + l]
// One LDS.128 yields two b64 pairs matching the x float4's natural b64 halves,
// feeding packed fma.rn.f32x2 with ZERO pack/unpack instructions.
// 1 token per lane: 9 packed accumulators = 18 regs -> fits 3 CTAs/SM.

// Scratch (no device allocations allowed)
__device__ int g_cnt[BB];        // valid count per batch
__device__ int g_src[BB * SS];   // per-batch: src token index for dest d

#define FMA2(d, a, b) asm("fma.rn.f32x2 %0, %1, %2, %0;" : "+l"(d) : "l"(a), "l"(b))
#define UNPACK2(lo, hi, v) asm("mov.b64 {%0, %1}, %2;" : "=f"(lo), "=f"(hi) : "l"(v))

// ---------------------------------------------------------------------------
// Kernel A: warp-per-batch ballot scan of valid_mask -> src map + counts.
// ---------------------------------------------------------------------------
__global__ __launch_bounds__(1024) void scan_kernel(const int* __restrict__ mask) {
    int warp = (blockIdx.x * 1024 + threadIdx.x) >> 5;   // 0..63 = batch
    int lane = threadIdx.x & 31;
    if (warp >= BB) return;
    const int* mrow = mask + warp * SS;
    int base = 0;
#pragma unroll
    for (int it = 0; it < SS / 32; it++) {
        int s = it * 32 + lane;
        int m = (mrow[s] == 1) ? 1 : 0;
        unsigned bits = __ballot_sync(0xffffffffu, m);
        if (m) g_src[warp * SS + base + __popc(bits & ((1u << lane) - 1u))] = s;
        base += __popc(bits);
    }
    if (lane == 0) g_cnt[warp] = base;
}

// ---------------------------------------------------------------------------
// Kernel B: main compute + item mapping + tail fill.
// 8 chunk-lanes x 4 token-lanes, 1 token/lane; packed f32x2 FMA over
// row pairs (lo = even rows, hi = odd rows). 3 CTAs/SM for latency hiding.
// ---------------------------------------------------------------------------
#define NBLK 444

__global__ __launch_bounds__(256, 3) void main_kernel(const float* __restrict__ seq,
                                                      const float* __restrict__ W,
                                                      const float* __restrict__ bias,
                                                      float* __restrict__ out) {
    __shared__ float Ws[SPLIT * WREG];    // ~27.8 KB
    __shared__ float Bs[LL];
    __shared__ int praw[BB];
    __shared__ int pref[BB + 1];          // pref[b] = sum cnt[0..b-1]; pref[BB]=total
    __shared__ int sitem[8][4];           // per-warp staged items

    int tid = threadIdx.x;
    int wid = tid >> 5, lane = tid & 31;
    if (tid < LL) Bs[tid] = bias[tid];
    if (tid < BB) praw[tid] = g_cnt[tid];

    // W preamble: warp wid fills chunk region wid (no divisions by WREG)
    {
        float* dst = &Ws[wid * WREG];
        for (int r = lane; r < NQ * LL * 4; r += 32) {
            int quad = r >> 2;              // q*9 + l
            int j = r & 3;
            int q = quad / LL, l = quad - q * LL;
            int g = q * 32 + wid * 4 + j;
            dst[r] = W[g * LL + l];
        }
    }
    __syncthreads();

    // warp-parallel exclusive prefix over 64 counts (warp 0 only)
    if (tid < 32) {
        int v0 = praw[tid];
        int v1 = praw[32 + tid];
#pragma unroll
        for (int o = 1; o < 32; o <<= 1) {
            int t0 = __shfl_up_sync(0xffffffffu, v0, o);
            int t1 = __shfl_up_sync(0xffffffffu, v1, o);
            if (tid >= o) { v0 += t0; v1 += t1; }
        }
        int sum0 = __shfl_sync(0xffffffffu, v0, 31);
        v1 += sum0;
        pref[tid + 1] = v0;
        pref[tid + 33] = v1;
        if (tid == 0) pref[0] = 0;
    }
    __syncthreads();

    int total = pref[BB];
    int n_sg = (total + 3) >> 2;   // supergroups of 4 work items

    int t_in = lane >> 3;   // token-lane 0..3
    int c    = lane & 7;    // chunk 0..7
    int wbase = c * WREG;

    // transposed warp index: spreads work imbalance across every SM's warps
    int warp_g = wid * NBLK + blockIdx.x;
    int nwarps = NBLK * 8;

    for (int sg = warp_g; sg < n_sg; sg += nwarps) {
        // ---- item mapping: lanes 0..3 search; results via smem ----
        int ii = sg * 4 + lane;
        if (lane < 4) {
            int q = (ii < total) ? ii : (total - 1);
            int b = 0;
#pragma unroll
            for (int st = 32; st >= 1; st >>= 1) {
                int mb = b + st;
                if (mb <= BB - 1 && pref[mb] <= q) b = mb;
            }
            int d = q - pref[b];
            int s = g_src[b * SS + d];
            sitem[wid][lane] = (b << 18) | (d << 9) | s;
        }
        __syncwarp();

        int i1 = sg * 4 + t_in;
        bool active = i1 < total;
        int item = sitem[wid][t_in];
        int b1 = item >> 18, d1 = (item >> 9) & 511, s1 = item & 511;

        const ulonglong2* xp = (const ulonglong2*)(seq + (size_t)(b1 * SS + s1) * HH);

        // packed accumulators: lo = even-row partials, hi = odd-row partials
        unsigned long long accP[LL];
#pragma unroll
        for (int l = 0; l < LL; l++) accP[l] = 0ull;

        ulonglong2 A, B;

#define CONSUME(X, Q)                                                          \
        {                                                                      \
            _Pragma("unroll") for (int l = 0; l < LL; l++) {                   \
                ulonglong2 wq = *(const ulonglong2*)&Ws[wbase + ((Q) * LL + l) * 4]; \
                FMA2(accP[l], X.x, wq.x);                                      \
                FMA2(accP[l], X.y, wq.y);                                      \
            }                                                                  \
        }

        // stage q: this lane reads 16B index q*8 + c (coalesced per token)
        A = xp[c];
#pragma unroll
        for (int q = 0; q < NQ; q += 2) {
            B = xp[(q + 1) * 8 + c];
            CONSUME(A, q);
            if (q + 2 < NQ) A = xp[(q + 2) * 8 + c];
            CONSUME(B, q + 1);
        }
#undef CONSUME

        // fold packed lanes, then reduce over the 8 chunk lanes (xor 1,2,4)
        float acc[LL];
#pragma unroll
        for (int l = 0; l < LL; l++) {
            float lo, hi;
            UNPACK2(lo, hi, accP[l]);
            acc[l] = lo + hi;
        }
#pragma unroll
        for (int o = 1; o <= 4; o <<= 1) {
#pragma unroll
            for (int l = 0; l < LL; l++)
                acc[l] += __shfl_xor_sync(0xffffffffu, acc[l], o);
        }

        if (active && c == 0) {
            float v[LL];
#pragma unroll
            for (int l = 0; l < LL; l++) v[l] = acc[l] + Bs[l];
            float m = v[0];
#pragma unroll
            for (int l = 1; l < LL; l++) m = fmaxf(m, v[l]);
            float sum = 0.f;
#pragma unroll
            for (int l = 0; l < LL; l++) { v[l] = __expf(v[l] - m); sum += v[l]; }
            float r = 1.f / sum;
            float* op = out + (size_t)(b1 * SS + d1) * LL;
#pragma unroll
            for (int l = 0; l < LL; l++) op[l] = v[l] * r;
        }
        __syncwarp();   // protect sitem before next iteration
    }

    // ---- tail fill: invalid dest slots get softmax(bias) constant ----
    int n_tail = BB * SS - total;
    if (n_tail > 0) {
        float bv[LL];
#pragma unroll
        for (int l = 0; l < LL; l++) bv[l] = Bs[l];
        float mx = bv[0];
#pragma unroll
        for (int l = 1; l < LL; l++) mx = fmaxf(mx, bv[l]);
        float sum = 0.f;
#pragma unroll
        for (int l = 0; l < LL; l++) { bv[l] = __expf(bv[l] - mx); sum += bv[l]; }
        float r = 1.f / sum;
#pragma unroll
        for (int l = 0; l < LL; l++) bv[l] *= r;

        int gtid = blockIdx.x * 256 + tid;
        int gsz = NBLK * 256;
        for (int j = gtid; j < n_tail; j += gsz) {
            // largest b with tpref(b) = b*SS - pref[b] <= j
            int b = 0;
#pragma unroll
            for (int st = 32; st >= 1; st >>= 1) {
                int m = b + st;
                if (m <= BB - 1 && (m * SS - pref[m]) <= j) b = m;
            }
            int d = (pref[b + 1] - pref[b]) + (j - (b * SS - pref[b]));
            float* op = out + (size_t)(b * SS + d) * LL;
#pragma unroll
            for (int l = 0; l < LL; l++) op[l] = bv[l];
        }
    }
}

// ---------------------------------------------------------------------------
extern "C" void kernel_launch(void* const* d_in, const int* in_sizes, int n_in,
                              void* d_out, int out_size) {
    const float* seq  = (const float*)d_in[0];   // [64,512,768] f32
    const int*   mask = (const int*)d_in[1];     // [64,512] i32
    const float* W    = (const float*)d_in[2];   // [768,9] f32
    const float* bias = (const float*)d_in[3];   // [9] f32
    float* out = (float*)d_out;                  // [64,512,9] f32

    scan_kernel<<<2, 1024>>>(mask);
    main_kernel<<<NBLK, 256>>>(seq, W, bias, out);
}

// round 16
// speedup vs baseline: 1.1758x; 1.1758x over previous
#include <cuda_runtime.h>
#include <cuda_bf16.h>
#include <math.h>

// Problem dims (fixed by dataset)
#define BB 64
#define SS 512
#define HH 768
#define LL 9

#define SPLIT 8                 // chunk lanes per token
#define HC (HH / SPLIT)         // 96 features per chunk
#define NQ (HH / 32)            // 24 stages (32 features each, 4 rows per chunk-lane)
#define WREG (HC * 8 + 4)       // 772 floats, mod 32 = 4 -> bank rotation
#define W8REG (HC + 4)          // 100 floats, mod 32 = 4

// Chunk c owns global rows { q*32 + c*4 + j : q in [0,24), j in [0,4) }.
// At stage q the 8 chunk lanes read float4 indices q*8+c -> one 128B line
// per token per stage (coalesced LDG, 4 lines per LDG.128 warp instruction).

// Scratch (no device allocations allowed)
__device__ int g_cnt[BB];        // valid count per batch
__device__ int g_src[BB * SS];   // per-batch: src token index for dest d

// ---------------------------------------------------------------------------
// Kernel A: warp-per-batch ballot scan of valid_mask -> src map + counts.
// ---------------------------------------------------------------------------
__global__ __launch_bounds__(1024) void scan_kernel(const int* __restrict__ mask) {
    int warp = (blockIdx.x * 1024 + threadIdx.x) >> 5;   // 0..63 = batch
    int lane = threadIdx.x & 31;
    if (warp >= BB) return;
    const int* mrow = mask + warp * SS;
    int base = 0;
#pragma unroll
    for (int it = 0; it < SS / 32; it++) {
        int s = it * 32 + lane;
        int m = (mrow[s] == 1) ? 1 : 0;
        unsigned bits = __ballot_sync(0xffffffffu, m);
        if (m) g_src[warp * SS + base + __popc(bits & ((1u << lane) - 1u))] = s;
        base += __popc(bits);
    }
    if (lane == 0) g_cnt[warp] = base;
}

// ---------------------------------------------------------------------------
// Kernel B: main compute + item mapping + tail fill.
// GEMV core: 8 chunk-lanes x 4 token-lanes, 2 tokens/lane sharing W LDS.
// Interleaved chunk->feature mapping for coalesced x loads.
// __launch_bounds__(256,3): cap regs at 85 -> 24 resident warps/SM for
// latency hiding (round-13 core was capped at 16 warps by 122 regs).
// ---------------------------------------------------------------------------
#define NBLK 444

__global__ __launch_bounds__(256, 3) void main_kernel(const float* __restrict__ seq,
                                                      const float* __restrict__ W,
                                                      const float* __restrict__ bias,
                                                      float* __restrict__ out) {
    __shared__ float Ws[SPLIT * WREG];    // cols 0..7, 8 floats/row  (~24.7 KB)
    __shared__ float W8s[SPLIT * W8REG];  // col 8, quad-packed       (~3.2 KB)
    __shared__ float Bs[LL];
    __shared__ int praw[BB];
    __shared__ int pref[BB + 1];          // pref[b] = sum cnt[0..b-1]; pref[BB]=total
    __shared__ int sitem[8][8];           // per-warp staged items

    int tid = threadIdx.x;
    if (tid < LL) Bs[tid] = bias[tid];
    if (tid < BB) praw[tid] = g_cnt[tid];
    // W preamble with interleaved row permutation:
    // region c, local row j -> global row g = (j>>2)*32 + c*4 + (j&3)
    for (int i = tid; i < SPLIT * WREG; i += 256) {
        int c = i / WREG, r = i % WREG;
        float val = 0.f;
        if (r < HC * 8) {
            int j = r / 8, col = r % 8;
            int g = ((j >> 2) << 5) + (c << 2) + (j & 3);
            val = W[g * LL + col];
        }
        Ws[i] = val;
    }
    for (int i = tid; i < SPLIT * W8REG; i += 256) {
        int c = i / W8REG, r = i % W8REG;
        float val = 0.f;
        if (r < HC) {
            int g = ((r >> 2) << 5) + (c << 2) + (r & 3);
            val = W[g * LL + 8];
        }
        W8s[i] = val;
    }
    __syncthreads();

    // warp-parallel exclusive prefix over 64 counts (warp 0 only)
    if (tid < 32) {
        int v0 = praw[tid];
        int v1 = praw[32 + tid];
#pragma unroll
        for (int o = 1; o < 32; o <<= 1) {
            int t0 = __shfl_up_sync(0xffffffffu, v0, o);
            int t1 = __shfl_up_sync(0xffffffffu, v1, o);
            if (tid >= o) { v0 += t0; v1 += t1; }
        }
        int sum0 = __shfl_sync(0xffffffffu, v0, 31);
        v1 += sum0;
        pref[tid + 1] = v0;
        pref[tid + 33] = v1;
        if (tid == 0) pref[0] = 0;
    }
    __syncthreads();

    int total = pref[BB];
    int n_sg = (total + 7) >> 3;   // supergroups of 8 work items

    int wid = tid >> 5, lane = tid & 31;
    int t_in = lane >> 3;   // token-lane 0..3
    int c    = lane & 7;    // chunk 0..7
    int wbase  = c * WREG;
    int w8base = c * W8REG;

    int warp_g = blockIdx.x * 8 + wid;
    int nwarps = NBLK * 8;

    for (int sg = warp_g; sg < n_sg; sg += nwarps) {
        // ---- item mapping: lanes 0..7 search; results via smem ----
        int ii = sg * 8 + lane;
        if (lane < 8) {
            int q = (ii < total) ? ii : (total - 1);
            int b = 0;
#pragma unroll
            for (int st = 32; st >= 1; st >>= 1) {
                int mb = b + st;
                if (mb <= BB - 1 && pref[mb] <= q) b = mb;
            }
            int d = q - pref[b];
            int s = g_src[b * SS + d];
            sitem[wid][lane] = (b << 18) | (d << 9) | s;
        }
        __syncwarp();

        int i1 = sg * 8 + t_in;
        int i2 = i1 + 4;
        bool a1 = i1 < total;
        bool a2 = i2 < total;
        int item1 = sitem[wid][t_in];
        int item2 = sitem[wid][t_in + 4];
        int b1 = item1 >> 18, d1 = (item1 >> 9) & 511, s1 = item1 & 511;
        int b2 = item2 >> 18, d2 = (item2 >> 9) & 511, s2 = item2 & 511;

        // base row pointers (no chunk offset: chunk selects within each stage)
        const float4* xp1 = (const float4*)(seq + (size_t)(b1 * SS + s1) * HH);
        const float4* xp2 = (const float4*)(seq + (size_t)(b2 * SS + s2) * HH);

        float acc1[LL], acc2[LL];
#pragma unroll
        for (int l = 0; l < LL; l++) { acc1[l] = 0.f; acc2[l] = 0.f; }

        float4 A1, A2, B1, B2;

#define CONSUME(X1, X2, Q)                                                     \
        {                                                                      \
            float4 w8q = *(const float4*)&W8s[w8base + (Q) * 4];               \
            float xs1_[4] = {X1.x, X1.y, X1.z, X1.w};                          \
            float xs2_[4] = {X2.x, X2.y, X2.z, X2.w};                          \
            float w8_[4] = {w8q.x, w8q.y, w8q.z, w8q.w};                       \
            _Pragma("unroll") for (int j = 0; j < 4; j++) {                    \
                int row = (Q) * 4 + j;                                         \
                const float4* wr = (const float4*)&Ws[wbase + row * 8];        \
                float4 w0 = wr[0];                                             \
                float4 w1 = wr[1];                                             \
                float xs1 = xs1_[j], xs2 = xs2_[j], w8 = w8_[j];               \
                acc1[0] = fmaf(xs1, w0.x, acc1[0]);                            \
                acc2[0] = fmaf(xs2, w0.x, acc2[0]);                            \
                acc1[1] = fmaf(xs1, w0.y, acc1[1]);                            \
                acc2[1] = fmaf(xs2, w0.y, acc2[1]);                            \
                acc1[2] = fmaf(xs1, w0.z, acc1[2]);                            \
                acc2[2] = fmaf(xs2, w0.z, acc2[2]);                            \
                acc1[3] = fmaf(xs1, w0.w, acc1[3]);                            \
                acc2[3] = fmaf(xs2, w0.w, acc2[3]);                            \
                acc1[4] = fmaf(xs1, w1.x, acc1[4]);                            \
                acc2[4] = fmaf(xs2, w1.x, acc2[4]);                            \
                acc1[5] = fmaf(xs1, w1.y, acc1[5]);                            \
                acc2[5] = fmaf(xs2, w1.y, acc2[5]);                            \
                acc1[6] = fmaf(xs1, w1.z, acc1[6]);                            \
                acc2[6] = fmaf(xs2, w1.z, acc2[6]);                            \
                acc1[7] = fmaf(xs1, w1.w, acc1[7]);                            \
                acc2[7] = fmaf(xs2, w1.w, acc2[7]);                            \
                acc1[8] = fmaf(xs1, w8, acc1[8]);                              \
                acc2[8] = fmaf(xs2, w8, acc2[8]);                              \
            }                                                                  \
        }

        // stage q: this lane reads float4 index q*8 + c (coalesced per token)
        A1 = xp1[c]; A2 = xp2[c];
#pragma unroll
        for (int q = 0; q < NQ; q += 2) {
            B1 = xp1[(q + 1) * 8 + c]; B2 = xp2[(q + 1) * 8 + c];
            CONSUME(A1, A2, q);
            if (q + 2 < NQ) { A1 = xp1[(q + 2) * 8 + c]; A2 = xp2[(q + 2) * 8 + c]; }
            CONSUME(B1, B2, q + 1);
        }
#undef CONSUME

        // reduce over the 8 chunk lanes (xor 1,2,4)
#pragma unroll
        for (int o = 1; o <= 4; o <<= 1) {
#pragma unroll
            for (int l = 0; l < LL; l++) {
                acc1[l] += __shfl_xor_sync(0xffffffffu, acc1[l], o);
                acc2[l] += __shfl_xor_sync(0xffffffffu, acc2[l], o);
            }
        }

        bool doit = (c == 0) ? a1 : ((c == 1) ? a2 : false);
        if (doit) {
            float v[LL];
            int slot;
            if (c == 0) {
#pragma unroll
                for (int l = 0; l < LL; l++) v[l] = acc1[l] + Bs[l];
                slot = b1 * SS + d1;
            } else {
#pragma unroll
                for (int l = 0; l < LL; l++) v[l] = acc2[l] + Bs[l];
                slot = b2 * SS + d2;
            }
            float m = v[0];
#pragma unroll
            for (int l = 1; l < LL; l++) m = fmaxf(m, v[l]);
            float sum = 0.f;
#pragma unroll
            for (int l = 0; l < LL; l++) { v[l] = __expf(v[l] - m); sum += v[l]; }
            float r = 1.f / sum;
            float* op = out + (size_t)slot * LL;
#pragma unroll
            for (int l = 0; l < LL; l++) op[l] = v[l] * r;
        }
        __syncwarp();   // protect sitem before next iteration
    }

    // ---- tail fill: invalid dest slots get softmax(bias) constant ----
    int n_tail = BB * SS - total;
    if (n_tail > 0) {
        float bv[LL];
#pragma unroll
        for (int l = 0; l < LL; l++) bv[l] = Bs[l];
        float mx = bv[0];
#pragma unroll
        for (int l = 1; l < LL; l++) mx = fmaxf(mx, bv[l]);
        float sum = 0.f;
#pragma unroll
        for (int l = 0; l < LL; l++) { bv[l] = __expf(bv[l] - mx); sum += bv[l]; }
        float r = 1.f / sum;
#pragma unroll
        for (int l = 0; l < LL; l++) bv[l] *= r;

        int gtid = blockIdx.x * 256 + tid;
        int gsz = NBLK * 256;
        for (int j = gtid; j < n_tail; j += gsz) {
            // largest b with tpref(b) = b*SS - pref[b] <= j
            int b = 0;
#pragma unroll
            for (int st = 32; st >= 1; st >>= 1) {
                int m = b + st;
                if (m <= BB - 1 && (m * SS - pref[m]) <= j) b = m;
            }
            int d = (pref[b + 1] - pref[b]) + (j - (b * SS - pref[b]));
            float* op = out + (size_t)(b * SS + d) * LL;
#pragma unroll
            for (int l = 0; l < LL; l++) op[l] = bv[l];
        }
    }
}

// ---------------------------------------------------------------------------
extern "C" void kernel_launch(void* const* d_in, const int* in_sizes, int n_in,
                              void* d_out, int out_size) {
    const float* seq  = (const float*)d_in[0];   // [64,512,768] f32
    const int*   mask = (const int*)d_in[1];     // [64,512] i32
    const float* W    = (const float*)d_in[2];   // [768,9] f32
    const float* bias = (const float*)d_in[3];   // [9] f32
    float* out = (float*)d_out;                  // [64,512,9] f32

    scan_kernel<<<2, 1024>>>(mask);
    main_kernel<<<NBLK, 256>>>(seq, W, bias, out);
}